// round 14
// baseline (speedup 1.0000x reference)
#include <cuda_runtime.h>
#include <math.h>

#define T_STEPS 512
#define B_SZ    64
#define HID     512
#define G3      1536
#define M_ROWS  (T_STEPS * B_SZ)          // 32768
#define OUT_TB  (T_STEPS * B_SZ * 1024)   // 33554432 floats

typedef unsigned long long ull;

// ---------------- device scratch (static: no allocations allowed) ----------------
__device__ float    g_gi[2L * M_ROWS * G3];         // [dir][t*B+b][1536]
__device__ float    g_h[2 * 2 * B_SZ * HID];        // [dir][parity][b][h]
__device__ unsigned g_bar2[2];                      // per-direction barrier counters

static __device__ __forceinline__ unsigned ld_acq(const unsigned* p) {
    unsigned v;
    asm volatile("ld.acquire.gpu.u32 %0, [%1];" : "=r"(v) : "l"(p));
    return v;
}
// pack a float into both halves of an f32x2 register
static __device__ __forceinline__ ull pk2(float v) {
    ull r;
    asm("mov.b64 %0, {%1, %1};" : "=l"(r) : "f"(v));
    return r;
}
static __device__ __forceinline__ float2 upk(ull v) {
    float2 f;
    asm("mov.b64 {%0, %1}, %2;" : "=f"(f.x), "=f"(f.y) : "l"(v));
    return f;
}
// packed dual-fp32 FMA (FFMA2 on sm_103a): d.lo += a.lo*b.lo; d.hi += a.hi*b.hi
static __device__ __forceinline__ void fma2(ull& d, ull a, ull b) {
    asm("fma.rn.f32x2 %0, %1, %2, %0;" : "+l"(d) : "l"(a), "l"(b));
}

// =====================================================================
// Kernel A: gi[dir][m][n] = inp[m][:] . Wih[n][:] + bih[n]
// M=32768, N=1536, K=512.  BM=BN=128, BK=16, 256 threads, 8x8 per thread
// (two 4-wide chunks per dim), FFMA2 accumulators paired along m.
// Staging stores XOR-swizzled (col = r ^ 8*kq) -> conflict-free STS;
// compute loads apply the same swizzle.
// =====================================================================
__global__ void __launch_bounds__(256, 2) gemm_in(
    const float* __restrict__ inp, const float* __restrict__ Wih,
    const float* __restrict__ bih, int dir)
{
    __shared__ float As[16 * 128];
    __shared__ float Bs[16 * 128];
    const int tid = threadIdx.x;
    const int m0 = blockIdx.y * 128;
    const int n0 = blockIdx.x * 128;
    const int mg = tid >> 4;          // 0..15
    const int ng = tid & 15;          // 0..15

    ull acc[4][8];
#pragma unroll
    for (int i = 0; i < 4; i++)
#pragma unroll
        for (int j = 0; j < 8; j++) acc[i][j] = 0ull;

    for (int k0 = 0; k0 < 512; k0 += 16) {
#pragma unroll
        for (int p = 0; p < 2; p++) {
            int v = tid + 256 * p;
            int r = v >> 2, kq = v & 3;
            float4 av = *(const float4*)(inp + (size_t)(m0 + r) * 512 + k0 + kq * 4);
            float4 bv = *(const float4*)(Wih + (size_t)(n0 + r) * 512 + k0 + kq * 4);
            int kb = kq * 4;
            int cs = r ^ (kq * 8);              // swizzled column
            As[(kb + 0) * 128 + cs] = av.x;  As[(kb + 1) * 128 + cs] = av.y;
            As[(kb + 2) * 128 + cs] = av.z;  As[(kb + 3) * 128 + cs] = av.w;
            Bs[(kb + 0) * 128 + cs] = bv.x;  Bs[(kb + 1) * 128 + cs] = bv.y;
            Bs[(kb + 2) * 128 + cs] = bv.z;  Bs[(kb + 3) * 128 + cs] = bv.w;
        }
        __syncthreads();
#pragma unroll
        for (int kk = 0; kk < 16; kk++) {
            int q8 = (kk >> 2) * 8;
            int xa = (4 * mg) ^ q8;
            int xb = (4 * ng) ^ q8;
            ulonglong2 a0 = *(const ulonglong2*)&As[kk * 128 + xa];
            ulonglong2 a1 = *(const ulonglong2*)&As[kk * 128 + 64 + xa];
            float4 b0 = *(const float4*)&Bs[kk * 128 + xb];
            float4 b1 = *(const float4*)&Bs[kk * 128 + 64 + xb];
            ull bp[8] = {pk2(b0.x), pk2(b0.y), pk2(b0.z), pk2(b0.w),
                         pk2(b1.x), pk2(b1.y), pk2(b1.z), pk2(b1.w)};
#pragma unroll
            for (int n = 0; n < 8; n++) {
                fma2(acc[0][n], a0.x, bp[n]);
                fma2(acc[1][n], a0.y, bp[n]);
                fma2(acc[2][n], a1.x, bp[n]);
                fma2(acc[3][n], a1.y, bp[n]);
            }
        }
        __syncthreads();
    }

    float bjv[8];
#pragma unroll
    for (int i = 0; i < 4; i++) {
        bjv[i]     = bih[n0 + 4 * ng + i];
        bjv[4 + i] = bih[n0 + 64 + 4 * ng + i];
    }
    float* op = g_gi + (size_t)dir * M_ROWS * G3;
#pragma unroll
    for (int p = 0; p < 4; p++) {
        int mlo = m0 + ((p >> 1) ? 64 : 0) + 4 * mg + (p & 1) * 2;   // rows mlo, mlo+1
        float2 v[8];
#pragma unroll
        for (int n = 0; n < 8; n++) v[n] = upk(acc[p][n]);
        size_t r0 = (size_t)mlo * G3 + n0 + 4 * ng;
        size_t r1 = (size_t)(mlo + 1) * G3 + n0 + 4 * ng;
        *(float4*)(op + r0)      = make_float4(v[0].x + bjv[0], v[1].x + bjv[1], v[2].x + bjv[2], v[3].x + bjv[3]);
        *(float4*)(op + r0 + 64) = make_float4(v[4].x + bjv[4], v[5].x + bjv[5], v[6].x + bjv[6], v[7].x + bjv[7]);
        *(float4*)(op + r1)      = make_float4(v[0].y + bjv[0], v[1].y + bjv[1], v[2].y + bjv[2], v[3].y + bjv[3]);
        *(float4*)(op + r1 + 64) = make_float4(v[4].y + bjv[4], v[5].y + bjv[5], v[6].y + bjv[6], v[7].y + bjv[7]);
    }
}

// =====================================================================
// Init: reset barriers, load h0 into parity-0 h buffers.
// =====================================================================
__global__ void init_k(const float* __restrict__ h0f, const float* __restrict__ h0b)
{
    int i = blockIdx.x * blockDim.x + threadIdx.x;
    if (i < 2) g_bar2[i] = 0u;
    if (i < B_SZ * HID) {
        g_h[i]         = h0f[i];   // dir0, parity0
        g_h[65536 + i] = h0b[i];   // dir1, parity0
    }
}

// =====================================================================
// Kernel B: persistent bidirectional GRU recurrence.
// 128 blocks (1/SM, all resident): dir = bx>>6, block owns 8 h-cols
// (24 Whh gate rows in smem, loaded once).
// 256 threads = 8 warps; warp w = k-slice [w*64, w*64+64) -> all lanes of a
// warp share k (w-operand broadcast). Lane: bg = lid&7 (b chunks 4bg & 32+4bg),
// cg = lid>>3 (c = cg*6..cg*6+5). FFMA2 pairs along b (pairs come packed
// from LDS.128). Full h staged once per step; partial buffer ghs aliases hs.
// smem: ws 512x32 (64KB) | hs 512x68 (136KB) = 200KB -> 1 block/SM.
// =====================================================================
#define WS_STR 32
#define HS_STR 68
#define GH_RSTR 72
#define GH_SLICE (24 * GH_RSTR)           // 1728 words per slice
#define SMEMB ((512 * WS_STR + 512 * HS_STR) * 4)   // 204800 B

__global__ void __launch_bounds__(256) gru_rec(
    const float* __restrict__ Whh_f, const float* __restrict__ Whh_b,
    const float* __restrict__ bhh_f, const float* __restrict__ bhh_b,
    float* __restrict__ out)
{
    extern __shared__ float sm[];
    float* ws  = sm;                     // [k 0..511][32]: c at cg*8+cc (cc<6)
    float* hs  = ws + 512 * WS_STR;      // [k 0..511][b] stride 68
    float* ghs = hs;                     // aliases hs (used after compute)

    const int bx  = blockIdx.x;
    const int dir = bx >> 6;
    const int j0  = (bx & 63) * 8;
    const int tid = threadIdx.x;
    const int w   = tid >> 5;            // warp = k-slice 0..7
    const int lid = tid & 31;
    const int bg  = lid & 7;
    const int cg  = lid >> 3;            // 0..3

    const float* Whh = dir ? Whh_b : Whh_f;
    const float* bhh = dir ? bhh_b : bhh_f;
    unsigned* bar = &g_bar2[dir];

    // Load this block's 24 Whh rows into ws[k][cg*8+cc], once.
    for (int idx = tid; idx < 24 * 512; idx += 256) {
        int c = idx >> 9, k = idx & 511;
        int gr = (c >> 3) * 512 + j0 + (c & 7);
        ws[k * WS_STR + (c / 6) * 8 + (c % 6)] = Whh[(size_t)gr * 512 + k];
    }
    __syncthreads();

    // Each thread finalizes outputs (b, jj) and (b+32, jj).
    const int ob  = tid >> 3;            // 0..31
    const int ojj = tid & 7;
    const float brr = bhh[j0 + ojj];
    const float bzz = bhh[512 + j0 + ojj];
    const float bnn = bhh[1024 + j0 + ojj];

    for (int s = 0; s < T_STEPS; s++) {
        const int par = s & 1;
        const float* hp = g_h + ((size_t)dir * 2 + par) * (B_SZ * HID);
        float* hw = g_h + ((size_t)dir * 2 + (1 - par)) * (B_SZ * HID);

        // Prefetch gi gate inputs for this step (consumed much later).
        const int tg = dir ? (511 - s) : s;
        const float* gip = g_gi + ((size_t)dir * T_STEPS + tg) * (B_SZ * G3);
        float pir[2], piz[2], pin[2];
#pragma unroll
        for (int u = 0; u < 2; u++) {
            const float* gp = gip + (size_t)(ob + u * 32) * G3 + j0 + ojj;
            pir[u] = __ldg(gp);
            piz[u] = __ldg(gp + 512);
            pin[u] = __ldg(gp + 1024);
        }

        // Stage full h (64 x 512) transposed into hs[k][b] stride 68.
        // lane b = tid&63 fixed; kv sweeps -> conflict-free STS (b spans banks).
#pragma unroll 8
        for (int w2 = 0; w2 < 32; w2++) {
            int v = tid + 256 * w2;
            int b = v & 63, kv = v >> 6;              // kv 0..127 (float4 col)
            float4 x = *(const float4*)(hp + (size_t)b * 512 + kv * 4);
            int ib = kv * 4;
            hs[(ib + 0) * HS_STR + b] = x.x;  hs[(ib + 1) * HS_STR + b] = x.y;
            hs[(ib + 2) * HS_STR + b] = x.z;  hs[(ib + 3) * HS_STR + b] = x.w;
        }
        __syncthreads();

        // Compute: this warp's 64 k-values. acc[4 b-pairs][6 c].
        ull acc[4][6];
#pragma unroll
        for (int i = 0; i < 4; i++)
#pragma unroll
            for (int j = 0; j < 6; j++) acc[i][j] = 0ull;

        const int kb = w * 64;
#pragma unroll 4
        for (int kk = 0; kk < 64; kk++) {
            int k = kb + kk;
            ulonglong2 h0 = *(const ulonglong2*)&hs[k * HS_STR + 4 * bg];        // b 4bg..+3
            ulonglong2 h1 = *(const ulonglong2*)&hs[k * HS_STR + 32 + 4 * bg];   // b 32+4bg..+3
            float4 w4 = *(const float4*)&ws[k * WS_STR + cg * 8];
            float2 w2v = *(const float2*)&ws[k * WS_STR + cg * 8 + 4];
            ull bp[6] = {pk2(w4.x), pk2(w4.y), pk2(w4.z), pk2(w4.w),
                         pk2(w2v.x), pk2(w2v.y)};
#pragma unroll
            for (int c = 0; c < 6; c++) {
                fma2(acc[0][c], h0.x, bp[c]);
                fma2(acc[1][c], h0.y, bp[c]);
                fma2(acc[2][c], h1.x, bp[c]);
                fma2(acc[3][c], h1.y, bp[c]);
            }
        }
        __syncthreads();   // hs free -> ghs (aliased) may be written

        // Store partials: ghs[w][c][b] stride 72.
        float* ghp = ghs + w * GH_SLICE;
#pragma unroll
        for (int c = 0; c < 6; c++) {
            int cgl = cg * 6 + c;
            float2 p0 = upk(acc[0][c]), p1 = upk(acc[1][c]);
            float2 p2 = upk(acc[2][c]), p3 = upk(acc[3][c]);
            *(float4*)&ghp[cgl * GH_RSTR + 4 * bg]      = make_float4(p0.x, p0.y, p1.x, p1.y);
            *(float4*)&ghp[cgl * GH_RSTR + 32 + 4 * bg] = make_float4(p2.x, p2.y, p3.x, p3.y);
        }
        __syncthreads();

        // Gate math: outputs (ob, ojj) and (ob+32, ojj).
#pragma unroll
        for (int u = 0; u < 2; u++) {
            int b = ob + u * 32;
            float gr = brr, gz = bzz, gn = bnn;
#pragma unroll
            for (int w8 = 0; w8 < 8; w8++) {
                const float* gq = ghs + w8 * GH_SLICE;
                gr += gq[ojj * GH_RSTR + b];
                gz += gq[(8 + ojj) * GH_RSTR + b];
                gn += gq[(16 + ojj) * GH_RSTR + b];
            }
            int j = j0 + ojj;
            float r = 1.f / (1.f + __expf(-(pir[u] + gr)));
            float z = 1.f / (1.f + __expf(-(piz[u] + gz)));
            float n = tanhf(pin[u] + r * gn);
            float hn = (1.f - z) * n + z * hp[(size_t)b * 512 + j];
            hw[(size_t)b * 512 + j] = hn;
            out[(size_t)tg * 65536 + (size_t)b * 1024 + dir * 512 + j] = hn;
            if (s == 511)
                out[(size_t)OUT_TB + dir * 32768 + b * 512 + j] = hn;
        }

        // Per-direction grid barrier (monotonic; 64 resident blocks/dir).
        __threadfence();
        __syncthreads();
        if (tid == 0) {
            atomicAdd(bar, 1u);
            unsigned target = (unsigned)(s + 1) * 64u;
            while (ld_acq(bar) < target) __nanosleep(64);
        }
        __syncthreads();
    }
}

// =====================================================================
extern "C" void kernel_launch(void* const* d_in, const int* in_sizes, int n_in,
                              void* d_out, int out_size)
{
    const float* inp   = (const float*)d_in[0];
    const float* h0f   = (const float*)d_in[1];
    const float* h0b   = (const float*)d_in[2];
    const float* Wih_f = (const float*)d_in[3];
    const float* Whh_f = (const float*)d_in[4];
    const float* bih_f = (const float*)d_in[5];
    const float* bhh_f = (const float*)d_in[6];
    const float* Wih_b = (const float*)d_in[7];
    const float* Whh_b = (const float*)d_in[8];
    const float* bih_b = (const float*)d_in[9];
    const float* bhh_b = (const float*)d_in[10];
    float* out = (float*)d_out;

    cudaFuncSetAttribute(gru_rec, cudaFuncAttributeMaxDynamicSharedMemorySize, SMEMB);

    init_k<<<128, 256>>>(h0f, h0b);
    dim3 ga(G3 / 128, M_ROWS / 128);
    gemm_in<<<ga, 256>>>(inp, Wih_f, bih_f, 0);
    gemm_in<<<ga, 256>>>(inp, Wih_b, bih_b, 1);
    gru_rec<<<128, 256, SMEMB>>>(Whh_f, Whh_b, bhh_f, bhh_b, out);
}

// round 16
// speedup vs baseline: 1.5899x; 1.5899x over previous
#include <cuda_runtime.h>
#include <math.h>

#define T_STEPS 512
#define B_SZ    64
#define HID     512
#define G3      1536
#define M_ROWS  (T_STEPS * B_SZ)          // 32768
#define OUT_TB  (T_STEPS * B_SZ * 1024)   // 33554432 floats

// ---------------- device scratch (static: no allocations allowed) ----------------
__device__ float    g_gi[2L * M_ROWS * G3];         // [dir][t*B+b][1536]
__device__ float    g_h[2 * 2 * B_SZ * HID];        // [dir][parity][b][h]
__device__ unsigned g_bar2[2];                      // per-direction barrier counters

static __device__ __forceinline__ unsigned ld_acq(const unsigned* p) {
    unsigned v;
    asm volatile("ld.acquire.gpu.u32 %0, [%1];" : "=r"(v) : "l"(p));
    return v;
}

// =====================================================================
// Kernel A: gi[dir][m][n] = inp[m][:] . Wih[n][:] + bih[n]
// M=32768, N=1536, K=512.  BM=BN=128, BK=16, 256 threads, scalar 8x8
// per-thread tile (two 4-wide chunks per dim).  Staging stores
// XOR-swizzled (col = r ^ 8*kq) -> conflict-free STS; compute loads
// apply the same swizzle. (Addressing validated by the R13 pass.)
// =====================================================================
__global__ void __launch_bounds__(256) gemm_in(
    const float* __restrict__ inp, const float* __restrict__ Wih,
    const float* __restrict__ bih, int dir)
{
    __shared__ float As[16 * 128];
    __shared__ float Bs[16 * 128];
    const int tid = threadIdx.x;
    const int m0 = blockIdx.y * 128;
    const int n0 = blockIdx.x * 128;
    const int mg = tid >> 4;          // 0..15
    const int ng = tid & 15;          // 0..15

    float acc[8][8];
#pragma unroll
    for (int i = 0; i < 8; i++)
#pragma unroll
        for (int j = 0; j < 8; j++) acc[i][j] = 0.f;

    for (int k0 = 0; k0 < 512; k0 += 16) {
#pragma unroll
        for (int p = 0; p < 2; p++) {
            int v = tid + 256 * p;
            int r = v >> 2, kq = v & 3;
            float4 av = *(const float4*)(inp + (size_t)(m0 + r) * 512 + k0 + kq * 4);
            float4 bv = *(const float4*)(Wih + (size_t)(n0 + r) * 512 + k0 + kq * 4);
            int kb = kq * 4;
            int cs = r ^ (kq * 8);              // swizzled column
            As[(kb + 0) * 128 + cs] = av.x;  As[(kb + 1) * 128 + cs] = av.y;
            As[(kb + 2) * 128 + cs] = av.z;  As[(kb + 3) * 128 + cs] = av.w;
            Bs[(kb + 0) * 128 + cs] = bv.x;  Bs[(kb + 1) * 128 + cs] = bv.y;
            Bs[(kb + 2) * 128 + cs] = bv.z;  Bs[(kb + 3) * 128 + cs] = bv.w;
        }
        __syncthreads();
#pragma unroll
        for (int kk = 0; kk < 16; kk++) {
            int q8 = (kk >> 2) * 8;
            int xa = (4 * mg) ^ q8;
            int xb = (4 * ng) ^ q8;
            float4 a0 = *(const float4*)&As[kk * 128 + xa];
            float4 a1 = *(const float4*)&As[kk * 128 + 64 + xa];
            float4 b0 = *(const float4*)&Bs[kk * 128 + xb];
            float4 b1 = *(const float4*)&Bs[kk * 128 + 64 + xb];
            const float aa[8] = {a0.x, a0.y, a0.z, a0.w, a1.x, a1.y, a1.z, a1.w};
            const float bb[8] = {b0.x, b0.y, b0.z, b0.w, b1.x, b1.y, b1.z, b1.w};
#pragma unroll
            for (int i = 0; i < 8; i++)
#pragma unroll
                for (int j = 0; j < 8; j++) acc[i][j] += aa[i] * bb[j];
        }
        __syncthreads();
    }

    float bjv[8];
#pragma unroll
    for (int j = 0; j < 4; j++) {
        bjv[j]     = bih[n0 + 4 * ng + j];
        bjv[4 + j] = bih[n0 + 64 + 4 * ng + j];
    }
    float* op = g_gi + (size_t)dir * M_ROWS * G3;
#pragma unroll
    for (int i = 0; i < 8; i++) {
        int mr = m0 + ((i < 4) ? (4 * mg + i) : (64 + 4 * mg + i - 4));
        size_t row = (size_t)mr * G3 + n0 + 4 * ng;
        *(float4*)(op + row)      = make_float4(acc[i][0] + bjv[0], acc[i][1] + bjv[1],
                                                acc[i][2] + bjv[2], acc[i][3] + bjv[3]);
        *(float4*)(op + row + 64) = make_float4(acc[i][4] + bjv[4], acc[i][5] + bjv[5],
                                                acc[i][6] + bjv[6], acc[i][7] + bjv[7]);
    }
}

// =====================================================================
// Init: reset barriers, load h0 into parity-0 h buffers.
// =====================================================================
__global__ void init_k(const float* __restrict__ h0f, const float* __restrict__ h0b)
{
    int i = blockIdx.x * blockDim.x + threadIdx.x;
    if (i < 2) g_bar2[i] = 0u;
    if (i < B_SZ * HID) {
        g_h[i]         = h0f[i];   // dir0, parity0
        g_h[65536 + i] = h0b[i];   // dir1, parity0
    }
}

// =====================================================================
// Kernel B: persistent bidirectional GRU recurrence (R12 structure +
// per-quarter named barriers for stage/compute overlap).
// 128 blocks: dir = bx>>6, each owns 8 h-cols (24 Whh gate rows in smem).
// 384 threads = 4 k-quarters x 96 threads (= 3 whole warps each).
// Quarter q stages ITS OWN 128 h-rows, bar.sync(q+1, 96), computes on
// them -> staging of one quarter overlaps compute of another; only ONE
// block-wide __syncthreads per step (before gate math) + grid barrier.
// All 128 blocks resident: 221184 B dyn smem -> 1 block/SM, 128 <= 148.
// smem: ws 512x28 | hs 512x68 | ghs 4x(24x64)
// =====================================================================
#define WSN   (512 * 28)
#define HSN   (512 * 68)
#define GHN   1536
#define SMEMB ((WSN + HSN + 4 * GHN) * 4)

__global__ void __launch_bounds__(384) gru_rec(
    const float* __restrict__ Whh_f, const float* __restrict__ Whh_b,
    const float* __restrict__ bhh_f, const float* __restrict__ bhh_b,
    float* __restrict__ out)
{
    extern __shared__ float sm[];
    float* ws  = sm;            // [k 0..511][c 0..27]
    float* hs  = ws + WSN;      // [k 0..511][b 0..63] stride 68
    float* ghs = hs + HSN;      // 4 quarters of [c 0..23][b 0..63]

    const int bx  = blockIdx.x;
    const int dir = bx >> 6;
    const int j0  = (bx & 63) * 8;
    const int tid = threadIdx.x;
    const int q    = tid / 96;        // k-quarter 0..3 (3 whole warps)
    const int htid = tid % 96;
    const int bg = htid & 15;         // b-group (4 rows)
    const int cg = htid / 16;         // c-group (4 cols), 0..5
    const int kbase = q * 128;

    const float* Whh = dir ? Whh_b : Whh_f;
    const float* bhh = dir ? bhh_b : bhh_f;
    unsigned* bar = &g_bar2[dir];

    // Load this block's 24 Whh rows into smem [k][c], once.
    for (int idx = tid; idx < 24 * 512; idx += 384) {
        int c = idx >> 9, k = idx & 511;
        int gr = (c >> 3) * 512 + j0 + (c & 7);
        ws[k * 28 + c] = Whh[(size_t)gr * 512 + k];
    }
    __syncthreads();

    // Gate-loop index precompute (each thread handles <=2 of 512 outputs).
    int gb_[2], gj_[2], gn_ = 0;
#pragma unroll
    for (int u = 0; u < 2; u++) {
        int idx = tid + u * 384;
        if (idx < 512) { gb_[gn_] = idx >> 3; gj_[gn_] = idx & 7; gn_++; }
    }

    for (int s = 0; s < T_STEPS; s++) {
        const int par = s & 1;
        const float* hp = g_h + ((size_t)dir * 2 + par) * (B_SZ * HID);
        float* hw = g_h + ((size_t)dir * 2 + (1 - par)) * (B_SZ * HID);

        // Prefetch this step's gi gate inputs (consumed much later).
        const int tg = dir ? (511 - s) : s;
        const float* gip = g_gi + ((size_t)dir * T_STEPS + tg) * (B_SZ * G3);
        float pir[2], piz[2], pin[2];
#pragma unroll
        for (int u = 0; u < 2; u++) {
            if (u < gn_) {
                const float* gp = gip + (size_t)gb_[u] * G3 + j0 + gj_[u];
                pir[u] = __ldg(gp);
                piz[u] = __ldg(gp + 512);
                pin[u] = __ldg(gp + 1024);
            }
        }

        // Stage THIS QUARTER's 128 h-rows (float4 cols q*32..q*32+31)
        // transposed into hs[k][b], stride 68. v layout: bits[0:2)=kv_lo,
        // [2:8)=b, [8:)=kv_hi -> 64B-coalesced GMEM reads.
#pragma unroll
        for (int w = 0; w < 22; w++) {
            int v = htid + w * 96;
            if (v < 2048) {
                int kv_lo = v & 3;
                int b     = (v >> 2) & 63;
                int kv_hi = v >> 8;                       // 0..7
                int kv = q * 32 + kv_hi * 4 + kv_lo;      // float4 col index
                float4 x = *(const float4*)(hp + (size_t)b * 512 + kv * 4);
                int ib = kv * 4;
                hs[(ib + 0) * 68 + b] = x.x;  hs[(ib + 1) * 68 + b] = x.y;
                hs[(ib + 2) * 68 + b] = x.z;  hs[(ib + 3) * 68 + b] = x.w;
            }
        }
        // Quarter-local barrier: 3 whole warps, id q+1.
        asm volatile("bar.sync %0, %1;" :: "r"(q + 1), "r"(96) : "memory");

        // GEMM quarter: acc[4][4] over its 128 k-values.
        float acc[4][4];
#pragma unroll
        for (int i = 0; i < 4; i++)
#pragma unroll
            for (int j = 0; j < 4; j++) acc[i][j] = 0.f;

#pragma unroll 8
        for (int kk = 0; kk < 128; kk++) {
            float4 h4 = *(const float4*)&hs[(kbase + kk) * 68 + bg * 4];
            float4 w4 = *(const float4*)&ws[(kbase + kk) * 28 + cg * 4];
            const float hh[4] = {h4.x, h4.y, h4.z, h4.w};
            const float wc[4] = {w4.x, w4.y, w4.z, w4.w};
#pragma unroll
            for (int i = 0; i < 4; i++)
#pragma unroll
                for (int j = 0; j < 4; j++) acc[i][j] += hh[i] * wc[j];
        }

        // Store partials for this quarter (ghs is NOT aliased -> no sync needed).
        float* ghp = ghs + q * GHN;
#pragma unroll
        for (int j = 0; j < 4; j++)
#pragma unroll
            for (int i = 0; i < 4; i++)
                ghp[(cg * 4 + j) * 64 + bg * 4 + i] = acc[i][j];

        // One block-wide sync: all quarters' partials visible.
        __syncthreads();

        // Gate math for this block's 8 h-columns (512 outputs).
#pragma unroll
        for (int u = 0; u < 2; u++) {
            if (u < gn_) {
                int b = gb_[u], jj = gj_[u];
                int j = j0 + jj;
                float gr = bhh[j], gz = bhh[512 + j], gn = bhh[1024 + j];
#pragma unroll
                for (int qq = 0; qq < 4; qq++) {
                    const float* gq = ghs + qq * GHN;
                    gr += gq[jj * 64 + b];
                    gz += gq[(8 + jj) * 64 + b];
                    gn += gq[(16 + jj) * 64 + b];
                }
                float r = 1.f / (1.f + __expf(-(pir[u] + gr)));
                float z = 1.f / (1.f + __expf(-(piz[u] + gz)));
                float n = tanhf(pin[u] + r * gn);
                float hn = (1.f - z) * n + z * hp[(size_t)b * 512 + j];
                hw[(size_t)b * 512 + j] = hn;
                out[(size_t)tg * 65536 + (size_t)b * 1024 + dir * 512 + j] = hn;
                if (s == 511)
                    out[(size_t)OUT_TB + dir * 32768 + b * 512 + j] = hn;
            }
        }

        // Per-direction grid barrier (monotonic; 64 resident blocks/dir).
        __threadfence();
        __syncthreads();
        if (tid == 0) {
            atomicAdd(bar, 1u);
            unsigned target = (unsigned)(s + 1) * 64u;
            while (ld_acq(bar) < target) __nanosleep(64);
        }
        __syncthreads();
    }
}

// =====================================================================
extern "C" void kernel_launch(void* const* d_in, const int* in_sizes, int n_in,
                              void* d_out, int out_size)
{
    const float* inp   = (const float*)d_in[0];
    const float* h0f   = (const float*)d_in[1];
    const float* h0b   = (const float*)d_in[2];
    const float* Wih_f = (const float*)d_in[3];
    const float* Whh_f = (const float*)d_in[4];
    const float* bih_f = (const float*)d_in[5];
    const float* bhh_f = (const float*)d_in[6];
    const float* Wih_b = (const float*)d_in[7];
    const float* Whh_b = (const float*)d_in[8];
    const float* bih_b = (const float*)d_in[9];
    const float* bhh_b = (const float*)d_in[10];
    float* out = (float*)d_out;

    cudaFuncSetAttribute(gru_rec, cudaFuncAttributeMaxDynamicSharedMemorySize, SMEMB);

    init_k<<<128, 256>>>(h0f, h0b);
    dim3 ga(G3 / 128, M_ROWS / 128);
    gemm_in<<<ga, 256>>>(inp, Wih_f, bih_f, 0);
    gemm_in<<<ga, 256>>>(inp, Wih_b, bih_b, 1);
    gru_rec<<<128, 384, SMEMB>>>(Whh_f, Whh_b, bhh_f, bhh_b, out);
}